// round 10
// baseline (speedup 1.0000x reference)
#include <cuda_runtime.h>
#include <cuda_bf16.h>
#include <cuda_fp16.h>
#include <stdint.h>

#define NP     4096
#define DF     256
#define TOPK   100
#define NCODES 32768     // full positive fp16 code space
#define HBLK   512       // histogram blocks; 32768 values each (u16-safe)

// ---- scratch (static device globals; no allocation in kernel_launch) ----
__device__ __nv_bfloat16 g_c1b[NP * DF];
__device__ __nv_bfloat16 g_c2b[NP * DF];
__device__ float         g_sq1[NP];
__device__ float         g_sq2[NP];
__device__ __half        g_d2h[(size_t)NP * NP];   // 32 MB fp16 squared distances
__device__ unsigned int  g_hist2[NCODES];          // exact per-fp16-code counts

__device__ __forceinline__ uint32_t smem_u32(const void* p) {
    uint32_t a;
    asm("{ .reg .u64 t; cvta.to.shared.u64 t, %1; cvt.u32.u64 %0, t; }" : "=r"(a) : "l"(p));
    return a;
}

#define LDSM_X4(r0, r1, r2, r3, addr)                                          \
    asm volatile("ldmatrix.sync.aligned.m8n8.x4.shared.b16 {%0,%1,%2,%3}, [%4];" \
        : "=r"(r0), "=r"(r1), "=r"(r2), "=r"(r3) : "r"(addr))

#define MMA16816(c, a0, a1, a2, a3, b0, b1)                                    \
    asm volatile("mma.sync.aligned.m16n8k16.row.col.f32.bf16.bf16.f32 "        \
        "{%0,%1,%2,%3}, {%4,%5,%6,%7}, {%8,%9}, {%0,%1,%2,%3};"                \
        : "+f"((c)[0]), "+f"((c)[1]), "+f"((c)[2]), "+f"((c)[3])               \
        : "r"(a0), "r"(a1), "r"(a2), "r"(a3), "r"(b0), "r"(b1))

// ---- dynamic SMEM layout for k_dist (bytes) ----
// K in 2 chunks of 128: tiles 128 rows x 136 bf16 (272 B rows, conflict-free ldmatrix)
#define PADROW  136
#define SM_SP   0                          // 128 f32
#define SM_SQ   512                        // 128 f32
#define SM_A    1024                       // 128*272 = 34816
#define SM_B    (SM_A + 128 * PADROW * 2)
#define SM_TOT  (SM_B + 128 * PADROW * 2)  // 70656 -> 2 CTAs/SM

// ================= kernels =================

__global__ void k_init() {
    int i = blockIdx.x * blockDim.x + threadIdx.x;
    if (i < NCODES) g_hist2[i] = 0u;
}

// gather picked rows (-> bf16 copies) + exact fp32 squared norms
__global__ void k_gather(const float* __restrict__ fm,
                         const int* __restrict__ ids1,
                         const int* __restrict__ ids2) {
    int row = blockIdx.x;
    const int* ids = blockIdx.y ? ids2 : ids1;
    __nv_bfloat16* C = blockIdx.y ? g_c2b : g_c1b;
    float*        SQ = blockIdx.y ? g_sq2 : g_sq1;

    int id = ids[row];
    float4 v = ((const float4*)(fm + (size_t)id * DF))[threadIdx.x];  // 64 thr * 4

    unsigned lo = ((unsigned)__bfloat16_as_ushort(__float2bfloat16(v.y)) << 16) |
                   (unsigned)__bfloat16_as_ushort(__float2bfloat16(v.x));
    unsigned hi = ((unsigned)__bfloat16_as_ushort(__float2bfloat16(v.w)) << 16) |
                   (unsigned)__bfloat16_as_ushort(__float2bfloat16(v.z));
    *(uint2*)&C[(size_t)row * DF + threadIdx.x * 4] = make_uint2(lo, hi);

    float s = v.x * v.x + v.y * v.y + v.z * v.z + v.w * v.w;
    #pragma unroll
    for (int o = 16; o; o >>= 1) s += __shfl_down_sync(0xffffffffu, s, o);
    __shared__ float ws[2];
    if ((threadIdx.x & 31) == 0) ws[threadIdx.x >> 5] = s;
    __syncthreads();
    if (threadIdx.x == 0) SQ[row] = ws[0] + ws[1];
}

// 128x128 tile of squared distances via bf16 mma.sync; pure GEMM + fp16 store
__global__ __launch_bounds__(256, 2) void k_dist() {
    extern __shared__ char sm[];
    const uint32_t sb = smem_u32(sm);
    const int t = threadIdx.x, lane = t & 31, w = t >> 5;
    const int p0 = blockIdx.y * 128, q0 = blockIdx.x * 128;

    if (t < 128)       ((float*)(sm + SM_SP))[t]       = g_sq1[p0 + t];
    else               ((float*)(sm + SM_SQ))[t - 128] = g_sq2[q0 + t - 128];

    const int mbase = (w & 3) * 32;     // 4 warps along M
    const int nbase = (w >> 2) * 64;    // 2 warps along N

    uint32_t aAddr[2], bAddr[4];
    #pragma unroll
    for (int i = 0; i < 2; i++) {
        int row = mbase + i * 16 + (lane & 15);
        aAddr[i] = sb + SM_A + row * (PADROW * 2) + (lane >> 4) * 16;
    }
    #pragma unroll
    for (int jp = 0; jp < 4; jp++) {
        int row = nbase + jp * 16 + (lane & 7) + ((lane >> 4) & 1) * 8;
        bAddr[jp] = sb + SM_B + row * (PADROW * 2) + ((lane >> 3) & 1) * 16;
    }

    float c[2][8][4];
    #pragma unroll
    for (int i = 0; i < 2; i++)
        #pragma unroll
        for (int j = 0; j < 8; j++)
            #pragma unroll
            for (int r = 0; r < 4; r++) c[i][j][r] = 0.f;

    for (int kc = 0; kc < 2; kc++) {
        #pragma unroll
        for (int i = 0; i < 8; i++) {
            int idx = i * 256 + t;
            int r = idx >> 4, cc = idx & 15;
            uint4 va = *(const uint4*)&g_c1b[(size_t)(p0 + r) * DF + kc * 128 + cc * 8];
            uint4 vb = *(const uint4*)&g_c2b[(size_t)(q0 + r) * DF + kc * 128 + cc * 8];
            *(uint4*)(sm + SM_A + r * (PADROW * 2) + cc * 16) = va;
            *(uint4*)(sm + SM_B + r * (PADROW * 2) + cc * 16) = vb;
        }
        __syncthreads();

        #pragma unroll
        for (int ks = 0; ks < 8; ks++) {
            const uint32_t ko = ks * 32;
            uint32_t a[2][4], b[8][2];
            #pragma unroll
            for (int i = 0; i < 2; i++)
                LDSM_X4(a[i][0], a[i][1], a[i][2], a[i][3], aAddr[i] + ko);
            #pragma unroll
            for (int jp = 0; jp < 4; jp++)
                LDSM_X4(b[2 * jp][0], b[2 * jp][1], b[2 * jp + 1][0], b[2 * jp + 1][1],
                        bAddr[jp] + ko);
            #pragma unroll
            for (int i = 0; i < 2; i++)
                #pragma unroll
                for (int j = 0; j < 8; j++)
                    MMA16816(c[i][j], a[i][0], a[i][1], a[i][2], a[i][3], b[j][0], b[j][1]);
        }
        __syncthreads();
    }

    // epilogue: d2 = sp + sq - 2*dot -> fp16 store
    const float* sps = (const float*)(sm + SM_SP);
    const float* sqs = (const float*)(sm + SM_SQ);
    #pragma unroll
    for (int i = 0; i < 2; i++) {
        const int r0 = mbase + i * 16 + (lane >> 2);
        const float sp0 = sps[r0], sp1 = sps[r0 + 8];
        #pragma unroll
        for (int j = 0; j < 8; j++) {
            const int cl = nbase + j * 8 + (lane & 3) * 2;
            const float sq0 = sqs[cl], sq1 = sqs[cl + 1];
            float d0 = fmaxf(sp0 + sq0 - 2.f * c[i][j][0], 0.f);
            float d1 = fmaxf(sp0 + sq1 - 2.f * c[i][j][1], 0.f);
            float d2v = fmaxf(sp1 + sq0 - 2.f * c[i][j][2], 0.f);
            float d3 = fmaxf(sp1 + sq1 - 2.f * c[i][j][3], 0.f);
            *(__half2*)&g_d2h[(size_t)(p0 + r0)     * NP + q0 + cl] = __floats2half2_rn(d0, d1);
            *(__half2*)&g_d2h[(size_t)(p0 + r0 + 8) * NP + q0 + cl] = __floats2half2_rn(d2v, d3);
        }
    }
}

// one-pass FULL-resolution histogram: 32768 fp16 codes as packed u16 pairs in smem
__global__ __launch_bounds__(256) void k_hist() {
    __shared__ unsigned h[NCODES / 2];            // 16384 words = 64 KB
    for (int i = threadIdx.x; i < NCODES / 2; i += 256) h[i] = 0u;
    __syncthreads();

    const uint4* p = (const uint4*)g_d2h;
    const size_t base = (size_t)blockIdx.x * (NP * (size_t)NP / HBLK / 8);
    #pragma unroll 4
    for (int r = 0; r < (int)(NP * (size_t)NP / HBLK / 8 / 256); r++) {  // 16 iters
        uint4 v = p[base + r * 256 + threadIdx.x];
        unsigned wd[4] = {v.x, v.y, v.z, v.w};
        #pragma unroll
        for (int k = 0; k < 4; k++) {
            unsigned lo = wd[k] & 0xFFFFu, hi = wd[k] >> 16;
            atomicAdd(&h[lo >> 1], 1u << ((lo & 1) * 16));
            atomicAdd(&h[hi >> 1], 1u << ((hi & 1) * 16));
        }
    }
    __syncthreads();
    for (int i = threadIdx.x; i < NCODES / 2; i += 256) {
        unsigned c = h[i];
        unsigned lo = c & 0xFFFFu, hi = c >> 16;
        if (lo) atomicAdd(&g_hist2[2 * i],     lo);
        if (hi) atomicAdd(&g_hist2[2 * i + 1], hi);
    }
}

// closed-form exact top-100: suffix scan over fp16 codes, weighted sqrt sum
__global__ __launch_bounds__(1024) void k_select(float* __restrict__ out) {
    __shared__ unsigned scan[1024];
    __shared__ float    part[1024];
    const int t = threadIdx.x;

    // thread t covers 32 codes descending: chi, chi-1, ..., chi-31
    const int chi = NCODES - 1 - 32 * t;
    unsigned cnt[32];
    unsigned csum = 0;
    #pragma unroll
    for (int j = 0; j < 32; j++) { cnt[j] = g_hist2[chi - j]; csum += cnt[j]; }

    scan[t] = csum;
    __syncthreads();
    #pragma unroll
    for (int o = 1; o < 1024; o <<= 1) {
        unsigned v = (t >= o) ? scan[t - o] : 0u;
        __syncthreads();
        if (t >= o) scan[t] += v;
        __syncthreads();
    }
    const unsigned excl = scan[t] - csum;   // total count in codes above this chunk

    float psum = 0.f;
    if (excl < TOPK) {
        unsigned quota = TOPK - excl;
        #pragma unroll
        for (int j = 0; j < 32; j++) {
            if (quota == 0) break;
            unsigned c = cnt[j];
            if (c) {
                unsigned take = c < quota ? c : quota;
                float val = __half2float(__ushort_as_half((unsigned short)(chi - j)));
                psum += (float)take * sqrtf(val);
                quota -= take;
            }
        }
    }
    part[t] = psum;
    __syncthreads();
    #pragma unroll
    for (int s = 512; s > 0; s >>= 1) {
        if (t < s) part[t] += part[t + s];
        __syncthreads();
    }
    if (t == 0) *out = part[0] / (float)TOPK;
}

extern "C" void kernel_launch(void* const* d_in, const int* in_sizes, int n_in,
                              void* d_out, int out_size) {
    const float* fm   = (const float*)d_in[0];
    const int*   ids1 = (const int*)d_in[1];
    const int*   ids2 = (const int*)d_in[2];
    float* out = (float*)d_out;

    static int smem_set = 0;
    if (!smem_set) {
        cudaFuncSetAttribute(k_dist, cudaFuncAttributeMaxDynamicSharedMemorySize, SM_TOT);
        smem_set = 1;
    }

    k_init<<<NCODES / 256, 256>>>();
    k_gather<<<dim3(NP, 2), 64>>>(fm, ids1, ids2);
    k_dist<<<dim3(NP / 128, NP / 128), 256, SM_TOT>>>();
    k_hist<<<HBLK, 256>>>();
    k_select<<<1, 1024>>>(out);
}

// round 11
// speedup vs baseline: 1.6797x; 1.6797x over previous
#include <cuda_runtime.h>
#include <cuda_bf16.h>
#include <cuda_fp16.h>
#include <stdint.h>

#define NP     4096
#define DF     256
#define TOPK   100
#define NBINS  2048      // coarse: fp16 bits >> 4
#define NCODES 32768     // fine: full positive fp16 code space

// ---- scratch (static device globals; no allocation in kernel_launch) ----
__device__ __nv_bfloat16 g_c1b[NP * DF];
__device__ __nv_bfloat16 g_c2b[NP * DF];
__device__ float         g_sq1[NP];
__device__ float         g_sq2[NP];
__device__ __half        g_d2h[(size_t)NP * NP];   // 32 MB fp16 squared distances
__device__ unsigned int  g_hist[NBINS];            // SAMPLED coarse histogram (1/8)
__device__ unsigned int  g_hist2[NCODES];          // exact per-code counts (candidates only)
__device__ int           g_threshBin;

__device__ __forceinline__ uint32_t smem_u32(const void* p) {
    uint32_t a;
    asm("{ .reg .u64 t; cvta.to.shared.u64 t, %1; cvt.u32.u64 %0, t; }" : "=r"(a) : "l"(p));
    return a;
}

#define LDSM_X4(r0, r1, r2, r3, addr)                                          \
    asm volatile("ldmatrix.sync.aligned.m8n8.x4.shared.b16 {%0,%1,%2,%3}, [%4];" \
        : "=r"(r0), "=r"(r1), "=r"(r2), "=r"(r3) : "r"(addr))

#define MMA16816(c, a0, a1, a2, a3, b0, b1)                                    \
    asm volatile("mma.sync.aligned.m16n8k16.row.col.f32.bf16.bf16.f32 "        \
        "{%0,%1,%2,%3}, {%4,%5,%6,%7}, {%8,%9}, {%0,%1,%2,%3};"                \
        : "+f"((c)[0]), "+f"((c)[1]), "+f"((c)[2]), "+f"((c)[3])               \
        : "r"(a0), "r"(a1), "r"(a2), "r"(a3), "r"(b0), "r"(b1))

// ---- dynamic SMEM layout for k_dist (bytes) ----
// K in 2 chunks of 128: tiles 128 rows x 136 bf16 (272 B rows, conflict-free ldmatrix)
#define PADROW  136
#define SM_HIST 0                          // 2048 x u32 = 8192 (sampled bins)
#define SM_SP   8192                       // 128 f32
#define SM_SQ   8704                       // 128 f32
#define SM_A    9216                       // 128*272 = 34816
#define SM_B    (SM_A + 128 * PADROW * 2)
#define SM_TOT  (SM_B + 128 * PADROW * 2)  // 78848 -> still 2 CTAs/SM

// ================= kernels =================

__global__ void k_init() {
    int i = blockIdx.x * blockDim.x + threadIdx.x;
    if (i < NBINS)  g_hist[i]  = 0u;
    if (i < NCODES) g_hist2[i] = 0u;
}

// gather picked rows (-> bf16 copies) + exact fp32 squared norms
__global__ void k_gather(const float* __restrict__ fm,
                         const int* __restrict__ ids1,
                         const int* __restrict__ ids2) {
    int row = blockIdx.x;
    const int* ids = blockIdx.y ? ids2 : ids1;
    __nv_bfloat16* C = blockIdx.y ? g_c2b : g_c1b;
    float*        SQ = blockIdx.y ? g_sq2 : g_sq1;

    int id = ids[row];
    float4 v = ((const float4*)(fm + (size_t)id * DF))[threadIdx.x];  // 64 thr * 4

    unsigned lo = ((unsigned)__bfloat16_as_ushort(__float2bfloat16(v.y)) << 16) |
                   (unsigned)__bfloat16_as_ushort(__float2bfloat16(v.x));
    unsigned hi = ((unsigned)__bfloat16_as_ushort(__float2bfloat16(v.w)) << 16) |
                   (unsigned)__bfloat16_as_ushort(__float2bfloat16(v.z));
    *(uint2*)&C[(size_t)row * DF + threadIdx.x * 4] = make_uint2(lo, hi);

    float s = v.x * v.x + v.y * v.y + v.z * v.z + v.w * v.w;
    #pragma unroll
    for (int o = 16; o; o >>= 1) s += __shfl_down_sync(0xffffffffu, s, o);
    __shared__ float ws[2];
    if ((threadIdx.x & 31) == 0) ws[threadIdx.x >> 5] = s;
    __syncthreads();
    if (threadIdx.x == 0) SQ[row] = ws[0] + ws[1];
}

// 128x128 tile: bf16 mma.sync GEMM + fp16 store + 1/8-sampled coarse histogram
__global__ __launch_bounds__(256, 2) void k_dist() {
    extern __shared__ char sm[];
    const uint32_t sb = smem_u32(sm);
    const int t = threadIdx.x, lane = t & 31, w = t >> 5;
    const int p0 = blockIdx.y * 128, q0 = blockIdx.x * 128;

    unsigned* hist = (unsigned*)(sm + SM_HIST);
    for (int i = t; i < NBINS; i += 256) hist[i] = 0u;
    if (t < 128)       ((float*)(sm + SM_SP))[t]       = g_sq1[p0 + t];
    else               ((float*)(sm + SM_SQ))[t - 128] = g_sq2[q0 + t - 128];

    const int mbase = (w & 3) * 32;     // 4 warps along M
    const int nbase = (w >> 2) * 64;    // 2 warps along N

    uint32_t aAddr[2], bAddr[4];
    #pragma unroll
    for (int i = 0; i < 2; i++) {
        int row = mbase + i * 16 + (lane & 15);
        aAddr[i] = sb + SM_A + row * (PADROW * 2) + (lane >> 4) * 16;
    }
    #pragma unroll
    for (int jp = 0; jp < 4; jp++) {
        int row = nbase + jp * 16 + (lane & 7) + ((lane >> 4) & 1) * 8;
        bAddr[jp] = sb + SM_B + row * (PADROW * 2) + ((lane >> 3) & 1) * 16;
    }

    float c[2][8][4];
    #pragma unroll
    for (int i = 0; i < 2; i++)
        #pragma unroll
        for (int j = 0; j < 8; j++)
            #pragma unroll
            for (int r = 0; r < 4; r++) c[i][j][r] = 0.f;

    for (int kc = 0; kc < 2; kc++) {
        #pragma unroll
        for (int i = 0; i < 8; i++) {
            int idx = i * 256 + t;
            int r = idx >> 4, cc = idx & 15;
            uint4 va = *(const uint4*)&g_c1b[(size_t)(p0 + r) * DF + kc * 128 + cc * 8];
            uint4 vb = *(const uint4*)&g_c2b[(size_t)(q0 + r) * DF + kc * 128 + cc * 8];
            *(uint4*)(sm + SM_A + r * (PADROW * 2) + cc * 16) = va;
            *(uint4*)(sm + SM_B + r * (PADROW * 2) + cc * 16) = vb;
        }
        __syncthreads();

        #pragma unroll
        for (int ks = 0; ks < 8; ks++) {
            const uint32_t ko = ks * 32;
            uint32_t a[2][4], b[8][2];
            #pragma unroll
            for (int i = 0; i < 2; i++)
                LDSM_X4(a[i][0], a[i][1], a[i][2], a[i][3], aAddr[i] + ko);
            #pragma unroll
            for (int jp = 0; jp < 4; jp++)
                LDSM_X4(b[2 * jp][0], b[2 * jp][1], b[2 * jp + 1][0], b[2 * jp + 1][1],
                        bAddr[jp] + ko);
            #pragma unroll
            for (int i = 0; i < 2; i++)
                #pragma unroll
                for (int j = 0; j < 8; j++)
                    MMA16816(c[i][j], a[i][0], a[i][1], a[i][2], a[i][3], b[j][0], b[j][1]);
        }
        __syncthreads();
    }

    // epilogue: d2 -> fp16 store; every 8th value feeds the sampled coarse hist
    const float* sps = (const float*)(sm + SM_SP);
    const float* sqs = (const float*)(sm + SM_SQ);
    #pragma unroll
    for (int i = 0; i < 2; i++) {
        const int r0 = mbase + i * 16 + (lane >> 2);
        const float sp0 = sps[r0], sp1 = sps[r0 + 8];
        #pragma unroll
        for (int j = 0; j < 8; j++) {
            const int cl = nbase + j * 8 + (lane & 3) * 2;
            const float sq0 = sqs[cl], sq1 = sqs[cl + 1];
            float d0 = fmaxf(sp0 + sq0 - 2.f * c[i][j][0], 0.f);
            float d1 = fmaxf(sp0 + sq1 - 2.f * c[i][j][1], 0.f);
            float d2v = fmaxf(sp1 + sq0 - 2.f * c[i][j][2], 0.f);
            float d3 = fmaxf(sp1 + sq1 - 2.f * c[i][j][3], 0.f);
            __half2 h01 = __floats2half2_rn(d0, d1);
            __half2 h23 = __floats2half2_rn(d2v, d3);
            if ((j & 1) == 0)    // deterministic 1/8 sample (j even, first of 4)
                atomicAdd(&hist[(*(unsigned*)&h01 & 0xFFFFu) >> 4], 1u);
            *(__half2*)&g_d2h[(size_t)(p0 + r0)     * NP + q0 + cl] = h01;
            *(__half2*)&g_d2h[(size_t)(p0 + r0 + 8) * NP + q0 + cl] = h23;
        }
    }
    __syncthreads();
    for (int i = t; i < NBINS; i += 256) {
        unsigned h = hist[i];
        if (h) atomicAdd(&g_hist[i], h);
    }
}

// suffix-scan threshold on the SAMPLED hist: sampled cum >= TOPK  =>  true cum >= TOPK
__global__ __launch_bounds__(1024) void k_thresh() {
    __shared__ unsigned scan[1024];
    const int t = threadIdx.x;
    const int btop = NBINS - 1 - 2 * t;
    unsigned h0 = g_hist[btop], h1 = g_hist[btop - 1];
    unsigned p = h0 + h1;
    scan[t] = p;
    __syncthreads();
    #pragma unroll
    for (int o = 1; o < 1024; o <<= 1) {
        unsigned v = (t >= o) ? scan[t - o] : 0u;
        __syncthreads();
        if (t >= o) scan[t] += v;
        __syncthreads();
    }
    unsigned excl = scan[t] - p;
    if (excl < TOPK && excl + p >= TOPK) {
        unsigned cum = excl + h0;
        g_threshBin = (cum >= TOPK) ? btop : btop - 1;
    }
}

// candidates (coarse bin >= threshold) -> exact per-code counts
__global__ void k_compact() {
    size_t i = (size_t)blockIdx.x * blockDim.x + threadIdx.x;
    const uint4 v = ((const uint4*)g_d2h)[i];      // 8 halves
    const unsigned tb = (unsigned)g_threshBin;
    unsigned words[4] = {v.x, v.y, v.z, v.w};
    #pragma unroll
    for (int wI = 0; wI < 4; wI++) {
        unsigned lo = words[wI] & 0xFFFFu, hi = words[wI] >> 16;
        if ((lo >> 4) >= tb) atomicAdd(&g_hist2[lo], 1u);
        if ((hi >> 4) >= tb) atomicAdd(&g_hist2[hi], 1u);
    }
}

// closed-form exact top-100: suffix scan over fp16 codes, weighted sqrt sum
__global__ __launch_bounds__(1024) void k_select(float* __restrict__ out) {
    __shared__ unsigned scan[1024];
    __shared__ float    part[1024];
    const int t = threadIdx.x;

    const int chi = NCODES - 1 - 32 * t;     // 32 codes descending per thread
    unsigned cnt[32];
    unsigned csum = 0;
    #pragma unroll
    for (int j = 0; j < 32; j++) { cnt[j] = g_hist2[chi - j]; csum += cnt[j]; }

    scan[t] = csum;
    __syncthreads();
    #pragma unroll
    for (int o = 1; o < 1024; o <<= 1) {
        unsigned v = (t >= o) ? scan[t - o] : 0u;
        __syncthreads();
        if (t >= o) scan[t] += v;
        __syncthreads();
    }
    const unsigned excl = scan[t] - csum;

    float psum = 0.f;
    if (excl < TOPK) {
        unsigned quota = TOPK - excl;
        #pragma unroll
        for (int j = 0; j < 32; j++) {
            if (quota == 0) break;
            unsigned c = cnt[j];
            if (c) {
                unsigned take = c < quota ? c : quota;
                float val = __half2float(__ushort_as_half((unsigned short)(chi - j)));
                psum += (float)take * sqrtf(val);
                quota -= take;
            }
        }
    }
    part[t] = psum;
    __syncthreads();
    #pragma unroll
    for (int s = 512; s > 0; s >>= 1) {
        if (t < s) part[t] += part[t + s];
        __syncthreads();
    }
    if (t == 0) *out = part[0] / (float)TOPK;
}

extern "C" void kernel_launch(void* const* d_in, const int* in_sizes, int n_in,
                              void* d_out, int out_size) {
    const float* fm   = (const float*)d_in[0];
    const int*   ids1 = (const int*)d_in[1];
    const int*   ids2 = (const int*)d_in[2];
    float* out = (float*)d_out;

    static int smem_set = 0;
    if (!smem_set) {
        cudaFuncSetAttribute(k_dist, cudaFuncAttributeMaxDynamicSharedMemorySize, SM_TOT);
        smem_set = 1;
    }

    k_init<<<NCODES / 256, 256>>>();
    k_gather<<<dim3(NP, 2), 64>>>(fm, ids1, ids2);
    k_dist<<<dim3(NP / 128, NP / 128), 256, SM_TOT>>>();
    k_thresh<<<1, 1024>>>();
    k_compact<<<(NP * NP / 8) / 256, 256>>>();   // uint4 = 8 halves per thread
    k_select<<<1, 1024>>>(out);
}

// round 12
// speedup vs baseline: 1.7191x; 1.0234x over previous
#include <cuda_runtime.h>
#include <cuda_bf16.h>
#include <cuda_fp16.h>
#include <stdint.h>

#define NP     4096
#define DF     256
#define TOPK   100
#define NBINS  2048      // coarse: fp16 bits >> 4
#define NCODES 32768     // fine: full positive fp16 code space

// ---- scratch (static device globals; no allocation in kernel_launch) ----
__device__ __nv_bfloat16 g_c1b[NP * DF];
__device__ __nv_bfloat16 g_c2b[NP * DF];
__device__ float         g_sq1[NP];
__device__ float         g_sq2[NP];
__device__ __half        g_d2h[(size_t)NP * NP];   // 32 MB fp16 squared distances
__device__ unsigned int  g_hist[NBINS];            // SAMPLED coarse histogram (1/8)
__device__ unsigned int  g_hist2[NCODES];          // exact per-code counts (candidates)
__device__ int           g_threshBin;

__device__ __forceinline__ uint32_t smem_u32(const void* p) {
    uint32_t a;
    asm("{ .reg .u64 t; cvta.to.shared.u64 t, %1; cvt.u32.u64 %0, t; }" : "=r"(a) : "l"(p));
    return a;
}

#define CP_ASYNC16(dst, src)                                                   \
    asm volatile("cp.async.cg.shared.global [%0], [%1], 16;" :: "r"(dst), "l"(src))
#define CP_COMMIT()  asm volatile("cp.async.commit_group;" ::: "memory")
#define CP_WAIT(n)   asm volatile("cp.async.wait_group %0;" :: "n"(n) : "memory")

#define LDSM_X4(r0, r1, r2, r3, addr)                                          \
    asm volatile("ldmatrix.sync.aligned.m8n8.x4.shared.b16 {%0,%1,%2,%3}, [%4];" \
        : "=r"(r0), "=r"(r1), "=r"(r2), "=r"(r3) : "r"(addr))

#define MMA16816(c, a0, a1, a2, a3, b0, b1)                                    \
    asm volatile("mma.sync.aligned.m16n8k16.row.col.f32.bf16.bf16.f32 "        \
        "{%0,%1,%2,%3}, {%4,%5,%6,%7}, {%8,%9}, {%0,%1,%2,%3};"                \
        : "+f"((c)[0]), "+f"((c)[1]), "+f"((c)[2]), "+f"((c)[3])               \
        : "r"(a0), "r"(a1), "r"(a2), "r"(a3), "r"(b0), "r"(b1))

// ---- dynamic SMEM layout for k_dist (bytes) ----
// K in 4 chunks of 64; per stage: A tile 128x128B (XOR-swizzled) + B tile.
#define SM_HIST 0                          // 2048 x u32 = 8192 (sampled bins)
#define SM_SP   8192                       // 128 f32
#define SM_SQ   8704                       // 128 f32
#define SM_T    9216                       // stages
#define STAGEB  32768                      // A(16K) + B(16K) per stage
#define SM_TOT  (SM_T + 2 * STAGEB)        // 74752 -> 2 CTAs/SM

// ================= kernels =================

// gather picked rows (-> bf16) + fp32 norms; first 136 y==0 blocks zero histograms
__global__ void k_gather(const float* __restrict__ fm,
                         const int* __restrict__ ids1,
                         const int* __restrict__ ids2) {
    int row = blockIdx.x;

    if (blockIdx.y == 0 && blockIdx.x < 136) {      // fused k_init
        int id = blockIdx.x * 64 + threadIdx.x;     // 0..8703
        #pragma unroll
        for (int j = 0; j < 4; j++) {
            int wI = id * 4 + j;                    // 0..34815
            if (wI < NBINS) g_hist[wI] = 0u;
            else if (wI < NBINS + NCODES) g_hist2[wI - NBINS] = 0u;
        }
    }

    const int* ids = blockIdx.y ? ids2 : ids1;
    __nv_bfloat16* C = blockIdx.y ? g_c2b : g_c1b;
    float*        SQ = blockIdx.y ? g_sq2 : g_sq1;

    int id = ids[row];
    float4 v = ((const float4*)(fm + (size_t)id * DF))[threadIdx.x];  // 64 thr * 4

    unsigned lo = ((unsigned)__bfloat16_as_ushort(__float2bfloat16(v.y)) << 16) |
                   (unsigned)__bfloat16_as_ushort(__float2bfloat16(v.x));
    unsigned hi = ((unsigned)__bfloat16_as_ushort(__float2bfloat16(v.w)) << 16) |
                   (unsigned)__bfloat16_as_ushort(__float2bfloat16(v.z));
    *(uint2*)&C[(size_t)row * DF + threadIdx.x * 4] = make_uint2(lo, hi);

    float s = v.x * v.x + v.y * v.y + v.z * v.z + v.w * v.w;
    #pragma unroll
    for (int o = 16; o; o >>= 1) s += __shfl_down_sync(0xffffffffu, s, o);
    __shared__ float ws[2];
    if ((threadIdx.x & 31) == 0) ws[threadIdx.x >> 5] = s;
    __syncthreads();
    if (threadIdx.x == 0) SQ[row] = ws[0] + ws[1];
}

// issue cp.async loads of K-chunk kc into stage stg (A and B tiles, swizzled)
__device__ __forceinline__ void load_chunk(uint32_t sb, int t, int p0, int q0,
                                           int stg, int kc) {
    const uint32_t baseA = sb + SM_T + stg * STAGEB;
    #pragma unroll
    for (int i = 0; i < 4; i++) {
        int idx = i * 256 + t;
        int row = idx >> 3, c = idx & 7;
        uint32_t off = row * 128 + (((unsigned)(c ^ (row & 7))) << 4);
        CP_ASYNC16(baseA + off,         &g_c1b[(size_t)(p0 + row) * DF + kc * 64 + c * 8]);
        CP_ASYNC16(baseA + 16384 + off, &g_c2b[(size_t)(q0 + row) * DF + kc * 64 + c * 8]);
    }
    CP_COMMIT();
}

// 128x128 tile: cp.async-pipelined bf16 mma.sync GEMM + fp16 store + sampled hist
__global__ __launch_bounds__(256, 2) void k_dist() {
    extern __shared__ char sm[];
    const uint32_t sb = smem_u32(sm);
    const int t = threadIdx.x, lane = t & 31, w = t >> 5;
    const int p0 = blockIdx.y * 128, q0 = blockIdx.x * 128;

    // prologue: start loading chunks 0,1 ASAP
    load_chunk(sb, t, p0, q0, 0, 0);
    load_chunk(sb, t, p0, q0, 1, 1);

    unsigned* hist = (unsigned*)(sm + SM_HIST);
    for (int i = t; i < NBINS; i += 256) hist[i] = 0u;
    if (t < 128)       ((float*)(sm + SM_SP))[t]       = g_sq1[p0 + t];
    else               ((float*)(sm + SM_SQ))[t - 128] = g_sq2[q0 + t - 128];

    const int mbase = (w & 3) * 32;     // 4 warps along M
    const int nbase = (w >> 2) * 64;    // 2 warps along N

    // ldmatrix address components (swizzled rows of 128 B)
    uint32_t aRow[2], bRow[4];
    unsigned aXor[2], bXor[4], aCb, bCb;
    aCb = lane >> 4;                    // 16B column bit for A
    bCb = (lane >> 3) & 1;              // 16B column bit for B
    #pragma unroll
    for (int i = 0; i < 2; i++) {
        int row = mbase + i * 16 + (lane & 15);
        aRow[i] = row * 128; aXor[i] = row & 7;
    }
    #pragma unroll
    for (int jp = 0; jp < 4; jp++) {
        int row = nbase + jp * 16 + (lane & 7) + ((lane >> 4) & 1) * 8;
        bRow[jp] = row * 128; bXor[jp] = row & 7;
    }

    float c[2][8][4];
    #pragma unroll
    for (int i = 0; i < 2; i++)
        #pragma unroll
        for (int j = 0; j < 8; j++)
            #pragma unroll
            for (int r = 0; r < 4; r++) c[i][j][r] = 0.f;

    #pragma unroll
    for (int k = 0; k < 4; k++) {
        if (k == 3) CP_WAIT(0); else CP_WAIT(1);
        __syncthreads();

        const uint32_t baseA = sb + SM_T + (k & 1) * STAGEB;
        const uint32_t baseB = baseA + 16384;

        #pragma unroll
        for (int ks = 0; ks < 4; ks++) {            // chunk K=64 -> 4 steps of 16
            uint32_t a[2][4], b[8][2];
            #pragma unroll
            for (int i = 0; i < 2; i++) {
                uint32_t off = ((unsigned)(((ks << 1) | aCb) ^ aXor[i])) << 4;
                LDSM_X4(a[i][0], a[i][1], a[i][2], a[i][3], baseA + aRow[i] + off);
            }
            #pragma unroll
            for (int jp = 0; jp < 4; jp++) {
                uint32_t off = ((unsigned)(((ks << 1) | bCb) ^ bXor[jp])) << 4;
                LDSM_X4(b[2 * jp][0], b[2 * jp][1], b[2 * jp + 1][0], b[2 * jp + 1][1],
                        baseB + bRow[jp] + off);
            }
            #pragma unroll
            for (int i = 0; i < 2; i++)
                #pragma unroll
                for (int j = 0; j < 8; j++)
                    MMA16816(c[i][j], a[i][0], a[i][1], a[i][2], a[i][3], b[j][0], b[j][1]);
        }
        __syncthreads();                            // all warps done reading stage
        if (k < 2) load_chunk(sb, t, p0, q0, k & 1, k + 2);
    }

    // epilogue: d2 -> fp16 store; every 8th value feeds the sampled coarse hist
    const float* sps = (const float*)(sm + SM_SP);
    const float* sqs = (const float*)(sm + SM_SQ);
    #pragma unroll
    for (int i = 0; i < 2; i++) {
        const int r0 = mbase + i * 16 + (lane >> 2);
        const float sp0 = sps[r0], sp1 = sps[r0 + 8];
        #pragma unroll
        for (int j = 0; j < 8; j++) {
            const int cl = nbase + j * 8 + (lane & 3) * 2;
            const float sq0 = sqs[cl], sq1 = sqs[cl + 1];
            float d0 = fmaxf(sp0 + sq0 - 2.f * c[i][j][0], 0.f);
            float d1 = fmaxf(sp0 + sq1 - 2.f * c[i][j][1], 0.f);
            float d2v = fmaxf(sp1 + sq0 - 2.f * c[i][j][2], 0.f);
            float d3 = fmaxf(sp1 + sq1 - 2.f * c[i][j][3], 0.f);
            __half2 h01 = __floats2half2_rn(d0, d1);
            __half2 h23 = __floats2half2_rn(d2v, d3);
            if ((j & 1) == 0)    // deterministic 1/8 sample
                atomicAdd(&hist[(*(unsigned*)&h01 & 0xFFFFu) >> 4], 1u);
            *(__half2*)&g_d2h[(size_t)(p0 + r0)     * NP + q0 + cl] = h01;
            *(__half2*)&g_d2h[(size_t)(p0 + r0 + 8) * NP + q0 + cl] = h23;
        }
    }
    __syncthreads();
    for (int i = t; i < NBINS; i += 256) {
        unsigned h = hist[i];
        if (h) atomicAdd(&g_hist[i], h);
    }
}

// single-warp early-exit threshold on the SAMPLED hist
__global__ void k_thresh() {
    const int lane = threadIdx.x;
    unsigned cum = 0;
    for (int b0 = NBINS - 1; b0 >= 31; b0 -= 32) {
        unsigned v = g_hist[b0 - lane];
        unsigned s = v;
        #pragma unroll
        for (int o = 1; o < 32; o <<= 1) {
            unsigned u = __shfl_up_sync(0xffffffffu, s, o);
            if (lane >= o) s += u;
        }
        unsigned tot = cum + s;
        unsigned ball = __ballot_sync(0xffffffffu, tot >= TOPK);
        if (ball) {
            int fl = __ffs(ball) - 1;
            if (lane == fl) g_threshBin = b0 - fl;
            return;
        }
        cum += __shfl_sync(0xffffffffu, s, 31);
    }
    if (lane == 0) g_threshBin = 0;
}

// candidates (coarse bin >= threshold) -> exact per-code counts
__global__ void k_compact() {
    size_t i = ((size_t)blockIdx.x * blockDim.x + threadIdx.x) * 2;
    const unsigned tb = (unsigned)g_threshBin;
    #pragma unroll
    for (int h = 0; h < 2; h++) {
        const uint4 v = ((const uint4*)g_d2h)[i + h];     // 8 halves
        unsigned words[4] = {v.x, v.y, v.z, v.w};
        #pragma unroll
        for (int wI = 0; wI < 4; wI++) {
            unsigned lo = words[wI] & 0xFFFFu, hi = words[wI] >> 16;
            if ((lo >> 4) >= tb) atomicAdd(&g_hist2[lo], 1u);
            if ((hi >> 4) >= tb) atomicAdd(&g_hist2[hi], 1u);
        }
    }
}

// closed-form exact top-100: suffix scan over fp16 codes, weighted sqrt sum
__global__ __launch_bounds__(1024) void k_select(float* __restrict__ out) {
    __shared__ unsigned scan[1024];
    __shared__ float    part[1024];
    const int t = threadIdx.x;

    const int chi = NCODES - 1 - 32 * t;     // 32 codes descending per thread
    unsigned cnt[32];
    unsigned csum = 0;
    #pragma unroll
    for (int j = 0; j < 32; j++) { cnt[j] = g_hist2[chi - j]; csum += cnt[j]; }

    scan[t] = csum;
    __syncthreads();
    #pragma unroll
    for (int o = 1; o < 1024; o <<= 1) {
        unsigned v = (t >= o) ? scan[t - o] : 0u;
        __syncthreads();
        if (t >= o) scan[t] += v;
        __syncthreads();
    }
    const unsigned excl = scan[t] - csum;

    float psum = 0.f;
    if (excl < TOPK) {
        unsigned quota = TOPK - excl;
        #pragma unroll
        for (int j = 0; j < 32; j++) {
            if (quota == 0) break;
            unsigned c = cnt[j];
            if (c) {
                unsigned take = c < quota ? c : quota;
                float val = __half2float(__ushort_as_half((unsigned short)(chi - j)));
                psum += (float)take * sqrtf(val);
                quota -= take;
            }
        }
    }
    part[t] = psum;
    __syncthreads();
    #pragma unroll
    for (int s = 512; s > 0; s >>= 1) {
        if (t < s) part[t] += part[t + s];
        __syncthreads();
    }
    if (t == 0) *out = part[0] / (float)TOPK;
}

extern "C" void kernel_launch(void* const* d_in, const int* in_sizes, int n_in,
                              void* d_out, int out_size) {
    const float* fm   = (const float*)d_in[0];
    const int*   ids1 = (const int*)d_in[1];
    const int*   ids2 = (const int*)d_in[2];
    float* out = (float*)d_out;

    static int smem_set = 0;
    if (!smem_set) {
        cudaFuncSetAttribute(k_dist, cudaFuncAttributeMaxDynamicSharedMemorySize, SM_TOT);
        smem_set = 1;
    }

    k_gather<<<dim3(NP, 2), 64>>>(fm, ids1, ids2);
    k_dist<<<dim3(NP / 128, NP / 128), 256, SM_TOT>>>();
    k_thresh<<<1, 32>>>();
    k_compact<<<(NP * NP / 16) / 256, 256>>>();   // 2 x uint4 = 16 halves / thread
    k_select<<<1, 1024>>>(out);
}

// round 13
// speedup vs baseline: 2.0316x; 1.1818x over previous
#include <cuda_runtime.h>
#include <cuda_bf16.h>
#include <cuda_fp16.h>
#include <stdint.h>

#define NP     4096
#define DF     256
#define TOPK   100
#define NBINS  2048      // coarse: fp16 bits >> 4
#define NCODES 32768     // fine: full positive fp16 code space
#define PREBLK 64        // sampled tiles (injective subset of the 32x32 grid)

// ---- scratch (static device globals; no allocation in kernel_launch) ----
__device__ __nv_bfloat16 g_c1b[NP * DF];
__device__ __nv_bfloat16 g_c2b[NP * DF];
__device__ float         g_sq1[NP];
__device__ float         g_sq2[NP];
__device__ unsigned int  g_hist[NBINS];            // sampled coarse histogram (1/16)
__device__ unsigned int  g_hist2[NCODES];          // exact per-code counts (candidates)
__device__ int           g_threshBin;

__device__ __forceinline__ uint32_t smem_u32(const void* p) {
    uint32_t a;
    asm("{ .reg .u64 t; cvta.to.shared.u64 t, %1; cvt.u32.u64 %0, t; }" : "=r"(a) : "l"(p));
    return a;
}

#define CP_ASYNC16(dst, src)                                                   \
    asm volatile("cp.async.cg.shared.global [%0], [%1], 16;" :: "r"(dst), "l"(src))
#define CP_COMMIT()  asm volatile("cp.async.commit_group;" ::: "memory")
#define CP_WAIT(n)   asm volatile("cp.async.wait_group %0;" :: "n"(n) : "memory")

#define LDSM_X4(r0, r1, r2, r3, addr)                                          \
    asm volatile("ldmatrix.sync.aligned.m8n8.x4.shared.b16 {%0,%1,%2,%3}, [%4];" \
        : "=r"(r0), "=r"(r1), "=r"(r2), "=r"(r3) : "r"(addr))

#define MMA16816(c, a0, a1, a2, a3, b0, b1)                                    \
    asm volatile("mma.sync.aligned.m16n8k16.row.col.f32.bf16.bf16.f32 "        \
        "{%0,%1,%2,%3}, {%4,%5,%6,%7}, {%8,%9}, {%0,%1,%2,%3};"                \
        : "+f"((c)[0]), "+f"((c)[1]), "+f"((c)[2]), "+f"((c)[3])               \
        : "r"(a0), "r"(a1), "r"(a2), "r"(a3), "r"(b0), "r"(b1))

// ---- dynamic SMEM layout (bytes) ----
#define SM_HIST 0                          // 2048 x u32 (pre-pass only)
#define SM_SP   8192                       // 128 f32
#define SM_SQ   8704                       // 128 f32
#define SM_T    9216                       // pipeline stages
#define STAGEB  32768                      // A(16K) + B(16K) per stage
#define SM_TOT  (SM_T + 2 * STAGEB)        // 74752 -> 2 CTAs/SM

// ================= kernels =================

// gather picked rows (-> bf16) + fp32 norms; fused zeroing of both histograms
__global__ __launch_bounds__(256) void k_gather(const float* __restrict__ fm,
                                                const int* __restrict__ ids1,
                                                const int* __restrict__ ids2) {
    if (blockIdx.y == 0 && blockIdx.x < 34) {       // fused init: 34816 words
        int id = blockIdx.x * 256 + threadIdx.x;
        #pragma unroll
        for (int j = 0; j < 4; j++) {
            int wI = id * 4 + j;
            if (wI < NBINS) g_hist[wI] = 0u;
            else if (wI < NBINS + NCODES) g_hist2[wI - NBINS] = 0u;
        }
    }

    const int g = threadIdx.x >> 6;                 // 4 rows per block
    const int lt = threadIdx.x & 63;
    const int row = blockIdx.x * 4 + g;
    const int* ids = blockIdx.y ? ids2 : ids1;
    __nv_bfloat16* C = blockIdx.y ? g_c2b : g_c1b;
    float*        SQ = blockIdx.y ? g_sq2 : g_sq1;

    int id = ids[row];
    float4 v = ((const float4*)(fm + (size_t)id * DF))[lt];

    unsigned lo = ((unsigned)__bfloat16_as_ushort(__float2bfloat16(v.y)) << 16) |
                   (unsigned)__bfloat16_as_ushort(__float2bfloat16(v.x));
    unsigned hi = ((unsigned)__bfloat16_as_ushort(__float2bfloat16(v.w)) << 16) |
                   (unsigned)__bfloat16_as_ushort(__float2bfloat16(v.z));
    *(uint2*)&C[(size_t)row * DF + lt * 4] = make_uint2(lo, hi);

    float s = v.x * v.x + v.y * v.y + v.z * v.z + v.w * v.w;
    #pragma unroll
    for (int o = 16; o; o >>= 1) s += __shfl_down_sync(0xffffffffu, s, o);
    __shared__ float ws[8];
    if ((threadIdx.x & 31) == 0) ws[threadIdx.x >> 5] = s;
    __syncthreads();
    if (lt == 0) SQ[row] = ws[g * 2] + ws[g * 2 + 1];
}

// issue cp.async loads of K-chunk kc into stage stg (A and B tiles, swizzled)
__device__ __forceinline__ void load_chunk(uint32_t sb, int t, int p0, int q0,
                                           int stg, int kc) {
    const uint32_t baseA = sb + SM_T + stg * STAGEB;
    #pragma unroll
    for (int i = 0; i < 4; i++) {
        int idx = i * 256 + t;
        int row = idx >> 3, c = idx & 7;
        uint32_t off = row * 128 + (((unsigned)(c ^ (row & 7))) << 4);
        CP_ASYNC16(baseA + off,         &g_c1b[(size_t)(p0 + row) * DF + kc * 64 + c * 8]);
        CP_ASYNC16(baseA + 16384 + off, &g_c2b[(size_t)(q0 + row) * DF + kc * 64 + c * 8]);
    }
    CP_COMMIT();
}

// 128x128 distance tile. PRE=1: sampled tiles -> coarse hist.
// PRE=0: all tiles -> threshold-filtered fine code counts (no d2 store at all).
template<int PRE>
__global__ __launch_bounds__(256, 2) void k_dist_t() {
    extern __shared__ char sm[];
    const uint32_t sb = smem_u32(sm);
    const int t = threadIdx.x, lane = t & 31, w = t >> 5;

    int bx, by;
    if (PRE) {   // injective 64-tile subset: (bx, bx + 16*(b>>5) mod 32)
        bx = blockIdx.x & 31;
        by = (bx + ((blockIdx.x >> 5) << 4)) & 31;
    } else {
        bx = blockIdx.x; by = blockIdx.y;
    }
    const int p0 = by * 128, q0 = bx * 128;

    load_chunk(sb, t, p0, q0, 0, 0);
    load_chunk(sb, t, p0, q0, 1, 1);

    unsigned* hist = (unsigned*)(sm + SM_HIST);
    if (PRE) for (int i = t; i < NBINS; i += 256) hist[i] = 0u;
    if (t < 128)       ((float*)(sm + SM_SP))[t]       = g_sq1[p0 + t];
    else               ((float*)(sm + SM_SQ))[t - 128] = g_sq2[q0 + t - 128];

    const int mbase = (w & 3) * 32;     // 4 warps along M
    const int nbase = (w >> 2) * 64;    // 2 warps along N

    uint32_t aRow[2], bRow[4];
    unsigned aXor[2], bXor[4];
    const unsigned aCb = lane >> 4, bCb = (lane >> 3) & 1;
    #pragma unroll
    for (int i = 0; i < 2; i++) {
        int row = mbase + i * 16 + (lane & 15);
        aRow[i] = row * 128; aXor[i] = row & 7;
    }
    #pragma unroll
    for (int jp = 0; jp < 4; jp++) {
        int row = nbase + jp * 16 + (lane & 7) + ((lane >> 4) & 1) * 8;
        bRow[jp] = row * 128; bXor[jp] = row & 7;
    }

    float c[2][8][4];
    #pragma unroll
    for (int i = 0; i < 2; i++)
        #pragma unroll
        for (int j = 0; j < 8; j++)
            #pragma unroll
            for (int r = 0; r < 4; r++) c[i][j][r] = 0.f;

    #pragma unroll
    for (int k = 0; k < 4; k++) {
        if (k == 3) CP_WAIT(0); else CP_WAIT(1);
        __syncthreads();

        const uint32_t baseA = sb + SM_T + (k & 1) * STAGEB;
        const uint32_t baseB = baseA + 16384;

        #pragma unroll
        for (int ks = 0; ks < 4; ks++) {
            uint32_t a[2][4], b[8][2];
            #pragma unroll
            for (int i = 0; i < 2; i++) {
                uint32_t off = ((unsigned)(((ks << 1) | aCb) ^ aXor[i])) << 4;
                LDSM_X4(a[i][0], a[i][1], a[i][2], a[i][3], baseA + aRow[i] + off);
            }
            #pragma unroll
            for (int jp = 0; jp < 4; jp++) {
                uint32_t off = ((unsigned)(((ks << 1) | bCb) ^ bXor[jp])) << 4;
                LDSM_X4(b[2 * jp][0], b[2 * jp][1], b[2 * jp + 1][0], b[2 * jp + 1][1],
                        baseB + bRow[jp] + off);
            }
            #pragma unroll
            for (int i = 0; i < 2; i++)
                #pragma unroll
                for (int j = 0; j < 8; j++)
                    MMA16816(c[i][j], a[i][0], a[i][1], a[i][2], a[i][3], b[j][0], b[j][1]);
        }
        __syncthreads();
        if (k < 2) load_chunk(sb, t, p0, q0, k & 1, k + 2);
    }

    const float* sps = (const float*)(sm + SM_SP);
    const float* sqs = (const float*)(sm + SM_SQ);
    const unsigned tc = PRE ? 0u : (((unsigned)g_threshBin) << 4);

    #pragma unroll
    for (int i = 0; i < 2; i++) {
        const int r0 = mbase + i * 16 + (lane >> 2);
        const float sp0 = sps[r0], sp1 = sps[r0 + 8];
        #pragma unroll
        for (int j = 0; j < 8; j++) {
            const int cl = nbase + j * 8 + (lane & 3) * 2;
            const float sq0 = sqs[cl], sq1 = sqs[cl + 1];
            float d0 = fmaxf(sp0 + sq0 - 2.f * c[i][j][0], 0.f);
            float d1 = fmaxf(sp0 + sq1 - 2.f * c[i][j][1], 0.f);
            float d2v = fmaxf(sp1 + sq0 - 2.f * c[i][j][2], 0.f);
            float d3 = fmaxf(sp1 + sq1 - 2.f * c[i][j][3], 0.f);
            __half2 h01 = __floats2half2_rn(d0, d1);
            __half2 h23 = __floats2half2_rn(d2v, d3);
            unsigned u01 = *(unsigned*)&h01, u23 = *(unsigned*)&h23;
            unsigned c0 = u01 & 0xFFFFu, c1 = u01 >> 16;
            unsigned c2 = u23 & 0xFFFFu, c3 = u23 >> 16;

            if (PRE) {        // coarse sampled histogram (all tile values)
                unsigned b0 = c0 >> 4, b1 = c1 >> 4, b2 = c2 >> 4, b3 = c3 >> 4;
                if (b0 == b1) atomicAdd(&hist[b0], 2u);
                else { atomicAdd(&hist[b0], 1u); atomicAdd(&hist[b1], 1u); }
                if (b2 == b3) atomicAdd(&hist[b2], 2u);
                else { atomicAdd(&hist[b2], 1u); atomicAdd(&hist[b3], 1u); }
            } else {          // rare threshold-filtered fine counts
                if (c0 >= tc) atomicAdd(&g_hist2[c0], 1u);
                if (c1 >= tc) atomicAdd(&g_hist2[c1], 1u);
                if (c2 >= tc) atomicAdd(&g_hist2[c2], 1u);
                if (c3 >= tc) atomicAdd(&g_hist2[c3], 1u);
            }
        }
    }
    if (PRE) {
        __syncthreads();
        for (int i = t; i < NBINS; i += 256) {
            unsigned h = hist[i];
            if (h) atomicAdd(&g_hist[i], h);
        }
    }
}

// single-warp early-exit threshold on the sampled hist
__global__ void k_thresh() {
    const int lane = threadIdx.x;
    unsigned cum = 0;
    for (int b0 = NBINS - 1; b0 >= 31; b0 -= 32) {
        unsigned v = g_hist[b0 - lane];
        unsigned s = v;
        #pragma unroll
        for (int o = 1; o < 32; o <<= 1) {
            unsigned u = __shfl_up_sync(0xffffffffu, s, o);
            if (lane >= o) s += u;
        }
        unsigned tot = cum + s;
        unsigned ball = __ballot_sync(0xffffffffu, tot >= TOPK);
        if (ball) {
            int fl = __ffs(ball) - 1;
            if (lane == fl) g_threshBin = b0 - fl;
            return;
        }
        cum += __shfl_sync(0xffffffffu, s, 31);
    }
    if (lane == 0) g_threshBin = 0;
}

// closed-form exact top-100: suffix scan over fp16 codes, weighted sqrt sum
__global__ __launch_bounds__(1024) void k_select(float* __restrict__ out) {
    __shared__ unsigned scan[1024];
    __shared__ float    part[1024];
    const int t = threadIdx.x;

    const int chi = NCODES - 1 - 32 * t;
    unsigned cnt[32];
    unsigned csum = 0;
    #pragma unroll
    for (int j = 0; j < 32; j++) { cnt[j] = g_hist2[chi - j]; csum += cnt[j]; }

    scan[t] = csum;
    __syncthreads();
    #pragma unroll
    for (int o = 1; o < 1024; o <<= 1) {
        unsigned v = (t >= o) ? scan[t - o] : 0u;
        __syncthreads();
        if (t >= o) scan[t] += v;
        __syncthreads();
    }
    const unsigned excl = scan[t] - csum;

    float psum = 0.f;
    if (excl < TOPK) {
        unsigned quota = TOPK - excl;
        #pragma unroll
        for (int j = 0; j < 32; j++) {
            if (quota == 0) break;
            unsigned c = cnt[j];
            if (c) {
                unsigned take = c < quota ? c : quota;
                float val = __half2float(__ushort_as_half((unsigned short)(chi - j)));
                psum += (float)take * sqrtf(val);
                quota -= take;
            }
        }
    }
    part[t] = psum;
    __syncthreads();
    #pragma unroll
    for (int s = 512; s > 0; s >>= 1) {
        if (t < s) part[t] += part[t + s];
        __syncthreads();
    }
    if (t == 0) *out = part[0] / (float)TOPK;
}

extern "C" void kernel_launch(void* const* d_in, const int* in_sizes, int n_in,
                              void* d_out, int out_size) {
    const float* fm   = (const float*)d_in[0];
    const int*   ids1 = (const int*)d_in[1];
    const int*   ids2 = (const int*)d_in[2];
    float* out = (float*)d_out;

    static int smem_set = 0;
    if (!smem_set) {
        cudaFuncSetAttribute(k_dist_t<0>, cudaFuncAttributeMaxDynamicSharedMemorySize, SM_TOT);
        cudaFuncSetAttribute(k_dist_t<1>, cudaFuncAttributeMaxDynamicSharedMemorySize, SM_TOT);
        smem_set = 1;
    }

    k_gather<<<dim3(NP / 4, 2), 256>>>(fm, ids1, ids2);
    k_dist_t<1><<<PREBLK, 256, SM_TOT>>>();                 // sampled pre-pass
    k_thresh<<<1, 32>>>();
    k_dist_t<0><<<dim3(NP / 128, NP / 128), 256, SM_TOT>>>(); // filtered main pass
    k_select<<<1, 1024>>>(out);
}